// round 7
// baseline (speedup 1.0000x reference)
#include <cuda_runtime.h>

// Problem dims
#define Bn   2
#define Tdim 2048
#define Cdim 1024
#define Hn   16
#define DKn  64
#define ND   1024   // H*DK == OUT
#define BT   4096   // Bn*Tdim

// Attention tiling
#define BR 128
#define BC 64
#define SMEM_ATTN ((2 * BC * DKn + BR * (BC + 1)) * 4)   // 66048 bytes

// Scratch (device globals: allocation-free per harness rules)
__device__ float g_q[Bn * Hn * Tdim * DKn];
__device__ float g_k[Bn * Hn * Tdim * DKn];
__device__ float g_v[Bn * Hn * Tdim * DKn];
__device__ float g_o[Bn * Tdim * ND];

// ---------------------------------------------------------------------------
// 128x128x8 register-tiled SGEMM, 256 threads, 8x8 microtile.
// MODE 0: A = x [BT x C], B selected by blockIdx.z (Wq/Wk/Wv), output written
//         into g_q/g_k/g_v in [B,H,T,DK] layout.
// MODE 1: A = g_o [BT x ND], B = W0 (linear_m1), plain row-major output.
// ---------------------------------------------------------------------------
template <int MODE>
__global__ void __launch_bounds__(256) gemm_kernel(const float* __restrict__ Ain,
                                                   const float* __restrict__ W0,
                                                   const float* __restrict__ W1,
                                                   const float* __restrict__ W2,
                                                   float* __restrict__ Cout)
{
    __shared__ float As[8][128];
    __shared__ float Bs[8][128];

    const int tid = threadIdx.x;
    const int tx  = tid & 15;
    const int ty  = tid >> 4;
    const int m0  = blockIdx.y * 128;
    const int n0  = blockIdx.x * 128;

    const float* A;
    const float* Bm;
    float* Out;
    if (MODE == 0) {
        A   = Ain;
        Bm  = (blockIdx.z == 0) ? W0 : (blockIdx.z == 1) ? W1 : W2;
        Out = (blockIdx.z == 0) ? g_q : (blockIdx.z == 1) ? g_k : g_v;
    } else {
        A   = g_o;
        Bm  = W0;
        Out = Cout;
    }

    const int arow = tid >> 1;          // 0..127
    const int akk  = (tid & 1) * 4;     // 0 or 4
    const int brow = tid >> 5;          // 0..7
    const int bcol = (tid & 31) * 4;    // 0..124

    const float* Aptr = A + (m0 + arow) * Cdim + akk;
    const float* Bptr = Bm + brow * ND + n0 + bcol;

    float4 aR = *(const float4*)Aptr;
    float4 bR = *(const float4*)Bptr;

    float acc[8][8];
#pragma unroll
    for (int i = 0; i < 8; i++)
#pragma unroll
        for (int j = 0; j < 8; j++) acc[i][j] = 0.0f;

    for (int k0 = 0; k0 < Cdim; k0 += 8) {
        __syncthreads();
        As[akk + 0][arow] = aR.x;
        As[akk + 1][arow] = aR.y;
        As[akk + 2][arow] = aR.z;
        As[akk + 3][arow] = aR.w;
        *(float4*)&Bs[brow][bcol] = bR;
        __syncthreads();

        if (k0 + 8 < Cdim) {           // prefetch next tile into registers
            aR = *(const float4*)(Aptr + k0 + 8);
            bR = *(const float4*)(Bptr + (k0 + 8) * ND);
        }

#pragma unroll
        for (int kk = 0; kk < 8; kk++) {
            float a[8], b[8];
            *(float4*)&a[0] = *(const float4*)&As[kk][ty * 8];
            *(float4*)&a[4] = *(const float4*)&As[kk][ty * 8 + 4];
            *(float4*)&b[0] = *(const float4*)&Bs[kk][tx * 8];
            *(float4*)&b[4] = *(const float4*)&Bs[kk][tx * 8 + 4];
#pragma unroll
            for (int i = 0; i < 8; i++)
#pragma unroll
                for (int j = 0; j < 8; j++)
                    acc[i][j] = fmaf(a[i], b[j], acc[i][j]);
        }
    }

#pragma unroll
    for (int i = 0; i < 8; i++) {
        const int row = m0 + ty * 8 + i;
        float4 lo = make_float4(acc[i][0], acc[i][1], acc[i][2], acc[i][3]);
        float4 hi = make_float4(acc[i][4], acc[i][5], acc[i][6], acc[i][7]);
        if (MODE == 0) {
            // row = b*T + t ; col n -> head h = n>>6, d = n&63
            const int b = row >> 11;
            const int t = row & (Tdim - 1);
            const int n = n0 + tx * 8;          // multiple of 8, never crosses a 64-boundary
            const int h = n >> 6;
            const int d = n & 63;
            float* dst = Out + (((b * Hn + h) * Tdim + t) << 6) + d;
            *(float4*)dst       = lo;
            *(float4*)(dst + 4) = hi;
        } else {
            float* dst = Out + row * ND + n0 + tx * 8;
            *(float4*)dst       = lo;
            *(float4*)(dst + 4) = hi;
        }
    }
}

// ---------------------------------------------------------------------------
// Flash attention, fp32, causal, scale = +sqrt(dk) = 8 (faithful to source).
// One block = 128 query rows of one (b,h); one thread owns one query row.
// K/V tiles (64x64) in shared; per-row score vector spilled to padded shared.
// ---------------------------------------------------------------------------
__global__ void __launch_bounds__(128) attn_kernel()
{
    extern __shared__ float sm[];
    float* Ks = sm;                    // BC*DKn
    float* Vs = sm + BC * DKn;         // BC*DKn
    float* Ss = sm + 2 * BC * DKn;     // BR*(BC+1), pad avoids bank conflicts

    const int bh  = blockIdx.y;        // b*H + h
    const int i0  = blockIdx.x * BR;
    const int tid = threadIdx.x;
    const int i   = i0 + tid;          // this thread's query row

    const float4* qrow = (const float4*)(g_q + (bh * Tdim + i) * DKn);
    float4 q4[16];
#pragma unroll
    for (int dd = 0; dd < 16; dd++) q4[dd] = qrow[dd];

    float4 o4[16];
#pragma unroll
    for (int dd = 0; dd < 16; dd++) o4[dd] = make_float4(0.f, 0.f, 0.f, 0.f);
    float m = -1e30f, l = 0.f;

    const int ntiles = (i0 + BR) / BC;
    const float4* kg0 = (const float4*)(g_k + bh * Tdim * DKn);
    const float4* vg0 = (const float4*)(g_v + bh * Tdim * DKn);
    float* srow = Ss + tid * (BC + 1);

    for (int tile = 0; tile < ntiles; tile++) {
        const int j0 = tile * BC;
        const float4* kg = kg0 + j0 * (DKn / 4);
        const float4* vg = vg0 + j0 * (DKn / 4);
#pragma unroll
        for (int r = 0; r < 8; r++) {           // 1024 float4 each, coalesced
            ((float4*)Ks)[tid + r * 128] = kg[tid + r * 128];
            ((float4*)Vs)[tid + r * 128] = vg[tid + r * 128];
        }
        __syncthreads();

        const int jlim = i - j0;                // valid keys: j <= jlim
        float tmax = -1e30f;
#pragma unroll 2
        for (int j = 0; j < BC; j++) {
            const float4* kr = (const float4*)(Ks + j * DKn);  // warp-broadcast reads
            float4 s4 = make_float4(0.f, 0.f, 0.f, 0.f);
#pragma unroll
            for (int dd = 0; dd < 16; dd++) {
                float4 kv = kr[dd];
                s4.x = fmaf(q4[dd].x, kv.x, s4.x);
                s4.y = fmaf(q4[dd].y, kv.y, s4.y);
                s4.z = fmaf(q4[dd].z, kv.z, s4.z);
                s4.w = fmaf(q4[dd].w, kv.w, s4.w);
            }
            float s = ((s4.x + s4.y) + (s4.z + s4.w)) * 8.0f;   // x sqrt(dk)
            if (j > jlim) s = -1e30f;                           // causal mask
            srow[j] = s;
            tmax = fmaxf(tmax, s);
        }

        const float mnew  = fmaxf(m, tmax);
        const float alpha = __expf(m - mnew);   // 0 on first live tile, 1 if max unchanged
#pragma unroll
        for (int dd = 0; dd < 16; dd++) {
            o4[dd].x *= alpha; o4[dd].y *= alpha;
            o4[dd].z *= alpha; o4[dd].w *= alpha;
        }
        float lsum = 0.f;
#pragma unroll 2
        for (int j = 0; j < BC; j++) {
            const float p = __expf(srow[j] - mnew);             // masked -> 0
            lsum += p;
            const float4* vr = (const float4*)(Vs + j * DKn);   // warp-broadcast reads
#pragma unroll
            for (int dd = 0; dd < 16; dd++) {
                float4 vv = vr[dd];
                o4[dd].x = fmaf(p, vv.x, o4[dd].x);
                o4[dd].y = fmaf(p, vv.y, o4[dd].y);
                o4[dd].z = fmaf(p, vv.z, o4[dd].z);
                o4[dd].w = fmaf(p, vv.w, o4[dd].w);
            }
        }
        l = l * alpha + lsum;
        m = mnew;
        __syncthreads();
    }

    const float inv = 1.0f / l;
    const int b = bh >> 4;
    const int h = bh & 15;
    float4* dst = (float4*)(g_o + (b * Tdim + i) * ND + h * DKn);
#pragma unroll
    for (int dd = 0; dd < 16; dd++) {
        float4 v = o4[dd];
        dst[dd] = make_float4(v.x * inv, v.y * inv, v.z * inv, v.w * inv);
    }
}

// ---------------------------------------------------------------------------
extern "C" void kernel_launch(void* const* d_in, const int* in_sizes, int n_in,
                              void* d_out, int out_size)
{
    const float* x  = (const float*)d_in[0];
    const float* Wq = (const float*)d_in[1];
    const float* Wk = (const float*)d_in[2];
    const float* Wv = (const float*)d_in[3];
    const float* Wo = (const float*)d_in[4];
    float* out = (float*)d_out;

    // Idempotent, host-side, deterministic: needed for 66 KB dynamic smem.
    cudaFuncSetAttribute(attn_kernel, cudaFuncAttributeMaxDynamicSharedMemorySize,
                         SMEM_ATTN);

    // Q/K/V projections: one GEMM grid, z selects weight matrix & destination.
    gemm_kernel<0><<<dim3(ND / 128, BT / 128, 3), 256>>>(x, Wq, Wk, Wv, nullptr);

    // Causal attention over all (b,h).
    attn_kernel<<<dim3(Tdim / BR, Bn * Hn), 128, SMEM_ATTN>>>();

    // Output projection: g_o [BT x ND] @ linear_m1 [ND x OUT].
    gemm_kernel<1><<<dim3(ND / 128, BT / 128, 1), 256>>>(nullptr, Wo, nullptr, nullptr, out);
}

// round 9
// speedup vs baseline: 1.0229x; 1.0229x over previous
#include <cuda_runtime.h>

// Problem dims
#define Bn   2
#define Tdim 2048
#define Cdim 1024
#define Hn   16
#define DKn  64
#define ND   1024   // H*DK == OUT
#define BT   4096   // Bn*Tdim
#define LDA  1024   // both GEMM A matrices and B matrices have 1024 stride

// Attention tiling
#define BR 128
#define BC 64
#define SMEM_ATTN ((2 * BC * DKn + BR * (BC + 1)) * 4)   // 66048 bytes

// A-tile padded stride: 132 floats = 528 bytes (16B-aligned rows, conflict-free)
#define ASTR 132

// Scratch (device globals: allocation-free per harness rules)
__device__ float g_q[Bn * Hn * Tdim * DKn];
__device__ float g_k[Bn * Hn * Tdim * DKn];
__device__ float g_v[Bn * Hn * Tdim * DKn];
__device__ float g_o[Bn * Tdim * ND];

// ---------------------------------------------------------------------------
// 128x128x16 register-tiled SGEMM, 256 threads, 8x8 microtile,
// double-buffered shared memory, ONE __syncthreads per k-iteration.
// MODE 0: A = x [BT x C], B selected by blockIdx.z (Wq/Wk/Wv), output written
//         into g_q/g_k/g_v in [B,H,T,DK] layout.
// MODE 1: A = g_o [BT x ND], B = W0 (linear_m1), plain row-major output.
// Thread (tx,ty) owns rows ty*8..+7 and cols {tx*4..+3} U {64+tx*4..+3}.
// ---------------------------------------------------------------------------
template <int MODE>
__global__ void __launch_bounds__(256, 2) gemm_kernel(const float* __restrict__ Ain,
                                                      const float* __restrict__ W0,
                                                      const float* __restrict__ W1,
                                                      const float* __restrict__ W2,
                                                      float* __restrict__ Cout)
{
    __shared__ float As[2][16][ASTR];  // k-major, stride 132 (16B-aligned rows)
    __shared__ float Bs[2][16][128];

    const int tid = threadIdx.x;
    const int tx  = tid & 15;
    const int ty  = tid >> 4;
    const int m0  = blockIdx.y * 128;
    const int n0  = blockIdx.x * 128;

    const float* A;
    const float* Bm;
    float* Out;
    if (MODE == 0) {
        A   = Ain;
        Bm  = (blockIdx.z == 0) ? W0 : (blockIdx.z == 1) ? W1 : W2;
        Out = (blockIdx.z == 0) ? g_q : (blockIdx.z == 1) ? g_k : g_v;
    } else {
        A   = g_o;
        Bm  = W0;
        Out = Cout;
    }

    // Loader mapping.
    // A tile: 128 rows x 16 k. Thread loads float4 at (arow, akk) and (arow, akk+8).
    const int arow = tid >> 1;           // 0..127
    const int akk  = (tid & 1) * 4;      // 0 or 4
    // B tile: 16 k-rows x 128 cols. Thread loads float4 at (brow, bcol), (brow+8, bcol).
    const int brow = tid >> 5;           // 0..7
    const int bcol = (tid & 31) * 4;     // 0..124

    const float* Aptr = A + (m0 + arow) * LDA + akk;
    const float* Bptr = Bm + brow * LDA + n0 + bcol;

    // Initial global fetch (k0 = 0)
    float4 a0 = *(const float4*)(Aptr);
    float4 a1 = *(const float4*)(Aptr + 8);
    float4 b0 = *(const float4*)(Bptr);
    float4 b1 = *(const float4*)(Bptr + 8 * LDA);

    // Stage into buffer 0
    As[0][akk + 0][arow] = a0.x;
    As[0][akk + 1][arow] = a0.y;
    As[0][akk + 2][arow] = a0.z;
    As[0][akk + 3][arow] = a0.w;
    As[0][akk + 8][arow] = a1.x;
    As[0][akk + 9][arow] = a1.y;
    As[0][akk + 10][arow] = a1.z;
    As[0][akk + 11][arow] = a1.w;
    *(float4*)&Bs[0][brow][bcol]     = b0;
    *(float4*)&Bs[0][brow + 8][bcol] = b1;
    __syncthreads();

    float acc[8][8];
#pragma unroll
    for (int i = 0; i < 8; i++)
#pragma unroll
        for (int j = 0; j < 8; j++) acc[i][j] = 0.0f;

    int buf = 0;
    for (int k0 = 16;; k0 += 16) {
        const bool more = (k0 < LDA);
        if (more) {                      // prefetch next tile into registers
            a0 = *(const float4*)(Aptr + k0);
            a1 = *(const float4*)(Aptr + k0 + 8);
            b0 = *(const float4*)(Bptr + k0 * LDA);
            b1 = *(const float4*)(Bptr + (k0 + 8) * LDA);
        }

#pragma unroll
        for (int kk = 0; kk < 16; kk++) {
            float a[8], b[8];
            *(float4*)&a[0] = *(const float4*)&As[buf][kk][ty * 8];
            *(float4*)&a[4] = *(const float4*)&As[buf][kk][ty * 8 + 4];
            *(float4*)&b[0] = *(const float4*)&Bs[buf][kk][tx * 4];
            *(float4*)&b[4] = *(const float4*)&Bs[buf][kk][64 + tx * 4];
#pragma unroll
            for (int i = 0; i < 8; i++)
#pragma unroll
                for (int j = 0; j < 8; j++)
                    acc[i][j] = fmaf(a[i], b[j], acc[i][j]);
        }

        if (!more) break;

        buf ^= 1;                        // stage prefetched tile into other buffer
        As[buf][akk + 0][arow] = a0.x;
        As[buf][akk + 1][arow] = a0.y;
        As[buf][akk + 2][arow] = a0.z;
        As[buf][akk + 3][arow] = a0.w;
        As[buf][akk + 8][arow] = a1.x;
        As[buf][akk + 9][arow] = a1.y;
        As[buf][akk + 10][arow] = a1.z;
        As[buf][akk + 11][arow] = a1.w;
        *(float4*)&Bs[buf][brow][bcol]     = b0;
        *(float4*)&Bs[buf][brow + 8][bcol] = b1;
        __syncthreads();
    }

    // Epilogue: two 4-wide column chunks per row (cols tx*4 and 64+tx*4).
#pragma unroll
    for (int i = 0; i < 8; i++) {
        const int row = m0 + ty * 8 + i;
        float4 lo = make_float4(acc[i][0], acc[i][1], acc[i][2], acc[i][3]);
        float4 hi = make_float4(acc[i][4], acc[i][5], acc[i][6], acc[i][7]);
        if (MODE == 0) {
            const int b = row >> 11;
            const int t = row & (Tdim - 1);
            const int n_lo = n0 + tx * 4;        // 4-wide chunk never crosses a head
            const int n_hi = n_lo + 64;
            float* dst_lo = Out + (((b * Hn + (n_lo >> 6)) * Tdim + t) << 6) + (n_lo & 63);
            float* dst_hi = Out + (((b * Hn + (n_hi >> 6)) * Tdim + t) << 6) + (n_hi & 63);
            *(float4*)dst_lo = lo;
            *(float4*)dst_hi = hi;
        } else {
            float* dst = Out + row * ND + n0 + tx * 4;
            *(float4*)dst        = lo;
            *(float4*)(dst + 64) = hi;
        }
    }
}

// ---------------------------------------------------------------------------
// Flash attention, fp32, causal, scale = +sqrt(dk) = 8 (faithful to source).
// One block = 128 query rows of one (b,h); one thread owns one query row.
// K/V tiles (64x64) in shared; per-row score vector spilled to padded shared.
// (unchanged from the passing R3 kernel)
// ---------------------------------------------------------------------------
__global__ void __launch_bounds__(128) attn_kernel()
{
    extern __shared__ float sm[];
    float* Ks = sm;                    // BC*DKn
    float* Vs = sm + BC * DKn;         // BC*DKn
    float* Ss = sm + 2 * BC * DKn;     // BR*(BC+1), pad avoids bank conflicts

    const int bh  = blockIdx.y;        // b*H + h
    const int i0  = blockIdx.x * BR;
    const int tid = threadIdx.x;
    const int i   = i0 + tid;          // this thread's query row

    const float4* qrow = (const float4*)(g_q + (bh * Tdim + i) * DKn);
    float4 q4[16];
#pragma unroll
    for (int dd = 0; dd < 16; dd++) q4[dd] = qrow[dd];

    float4 o4[16];
#pragma unroll
    for (int dd = 0; dd < 16; dd++) o4[dd] = make_float4(0.f, 0.f, 0.f, 0.f);
    float m = -1e30f, l = 0.f;

    const int ntiles = (i0 + BR) / BC;
    const float4* kg0 = (const float4*)(g_k + bh * Tdim * DKn);
    const float4* vg0 = (const float4*)(g_v + bh * Tdim * DKn);
    float* srow = Ss + tid * (BC + 1);

    for (int tile = 0; tile < ntiles; tile++) {
        const int j0 = tile * BC;
        const float4* kg = kg0 + j0 * (DKn / 4);
        const float4* vg = vg0 + j0 * (DKn / 4);
#pragma unroll
        for (int r = 0; r < 8; r++) {           // 1024 float4 each, coalesced
            ((float4*)Ks)[tid + r * 128] = kg[tid + r * 128];
            ((float4*)Vs)[tid + r * 128] = vg[tid + r * 128];
        }
        __syncthreads();

        const int jlim = i - j0;                // valid keys: j <= jlim
        float tmax = -1e30f;
#pragma unroll 2
        for (int j = 0; j < BC; j++) {
            const float4* kr = (const float4*)(Ks + j * DKn);  // warp-broadcast reads
            float4 s4 = make_float4(0.f, 0.f, 0.f, 0.f);
#pragma unroll
            for (int dd = 0; dd < 16; dd++) {
                float4 kv = kr[dd];
                s4.x = fmaf(q4[dd].x, kv.x, s4.x);
                s4.y = fmaf(q4[dd].y, kv.y, s4.y);
                s4.z = fmaf(q4[dd].z, kv.z, s4.z);
                s4.w = fmaf(q4[dd].w, kv.w, s4.w);
            }
            float s = ((s4.x + s4.y) + (s4.z + s4.w)) * 8.0f;   // x sqrt(dk)
            if (j > jlim) s = -1e30f;                           // causal mask
            srow[j] = s;
            tmax = fmaxf(tmax, s);
        }

        const float mnew  = fmaxf(m, tmax);
        const float alpha = __expf(m - mnew);   // 0 on first live tile, 1 if max unchanged
#pragma unroll
        for (int dd = 0; dd < 16; dd++) {
            o4[dd].x *= alpha; o4[dd].y *= alpha;
            o4[dd].z *= alpha; o4[dd].w *= alpha;
        }
        float lsum = 0.f;
#pragma unroll 2
        for (int j = 0; j < BC; j++) {
            const float p = __expf(srow[j] - mnew);             // masked -> 0
            lsum += p;
            const float4* vr = (const float4*)(Vs + j * DKn);   // warp-broadcast reads
#pragma unroll
            for (int dd = 0; dd < 16; dd++) {
                float4 vv = vr[dd];
                o4[dd].x = fmaf(p, vv.x, o4[dd].x);
                o4[dd].y = fmaf(p, vv.y, o4[dd].y);
                o4[dd].z = fmaf(p, vv.z, o4[dd].z);
                o4[dd].w = fmaf(p, vv.w, o4[dd].w);
            }
        }
        l = l * alpha + lsum;
        m = mnew;
        __syncthreads();
    }

    const float inv = 1.0f / l;
    const int b = bh >> 4;
    const int h = bh & 15;
    float4* dst = (float4*)(g_o + (b * Tdim + i) * ND + h * DKn);
#pragma unroll
    for (int dd = 0; dd < 16; dd++) {
        float4 v = o4[dd];
        dst[dd] = make_float4(v.x * inv, v.y * inv, v.z * inv, v.w * inv);
    }
}

// ---------------------------------------------------------------------------
extern "C" void kernel_launch(void* const* d_in, const int* in_sizes, int n_in,
                              void* d_out, int out_size)
{
    const float* x  = (const float*)d_in[0];
    const float* Wq = (const float*)d_in[1];
    const float* Wk = (const float*)d_in[2];
    const float* Wv = (const float*)d_in[3];
    const float* Wo = (const float*)d_in[4];
    float* out = (float*)d_out;

    // Idempotent, host-side, deterministic: needed for 66 KB dynamic smem.
    cudaFuncSetAttribute(attn_kernel, cudaFuncAttributeMaxDynamicSharedMemorySize,
                         SMEM_ATTN);

    // Q/K/V projections: one GEMM grid, z selects weight matrix & destination.
    gemm_kernel<0><<<dim3(ND / 128, BT / 128, 3), 256>>>(x, Wq, Wk, Wv, nullptr);

    // Causal attention over all (b,h).
    attn_kernel<<<dim3(Tdim / BR, Bn * Hn), 128, SMEM_ATTN>>>();

    // Output projection: g_o [BT x ND] @ linear_m1 [ND x OUT].
    gemm_kernel<1><<<dim3(ND / 128, BT / 128, 1), 256>>>(nullptr, Wo, nullptr, nullptr, out);
}

// round 11
// speedup vs baseline: 1.2234x; 1.1960x over previous
#include <cuda_runtime.h>

// Problem dims
#define Bn   2
#define Tdim 2048
#define Cdim 1024
#define Hn   16
#define DKn  64
#define ND   1024   // H*DK == OUT
#define BT   4096   // Bn*Tdim
#define LDA  1024   // both GEMM A matrices and B matrices have 1024 stride

// Attention tiling
#define BR 128
#define BC 64
#define NXBLK (Tdim / BR)                                // 16 row-blocks per (b,h)
#define NBH   (Bn * Hn)                                  // 32
#define SMEM_ATTN ((2 * BC * DKn + BR * (BC + 1)) * 4)   // 66048 bytes

// A-tile padded stride: 132 floats = 528 bytes (16B-aligned rows, conflict-free)
#define ASTR 132

// Scratch (device globals: allocation-free per harness rules)
__device__ float g_q[Bn * Hn * Tdim * DKn];
__device__ float g_k[Bn * Hn * Tdim * DKn];
__device__ float g_v[Bn * Hn * Tdim * DKn];
__device__ float g_o[Bn * Tdim * ND];

// ---------------------------------------------------------------------------
// 128x128x16 register-tiled SGEMM, 256 threads, 8x8 microtile,
// double-buffered shared memory, ONE __syncthreads per k-iteration.
// MODE 0: A = x [BT x C], B selected by blockIdx.z (Wq/Wk/Wv), output written
//         into g_q/g_k/g_v in [B,H,T,DK] layout.
// MODE 1: A = g_o [BT x ND], B = W0 (linear_m1), plain row-major output.
// ---------------------------------------------------------------------------
template <int MODE>
__global__ void __launch_bounds__(256, 2) gemm_kernel(const float* __restrict__ Ain,
                                                      const float* __restrict__ W0,
                                                      const float* __restrict__ W1,
                                                      const float* __restrict__ W2,
                                                      float* __restrict__ Cout)
{
    __shared__ float As[2][16][ASTR];  // k-major, stride 132 (16B-aligned rows)
    __shared__ float Bs[2][16][128];

    const int tid = threadIdx.x;
    const int tx  = tid & 15;
    const int ty  = tid >> 4;
    const int m0  = blockIdx.y * 128;
    const int n0  = blockIdx.x * 128;

    const float* A;
    const float* Bm;
    float* Out;
    if (MODE == 0) {
        A   = Ain;
        Bm  = (blockIdx.z == 0) ? W0 : (blockIdx.z == 1) ? W1 : W2;
        Out = (blockIdx.z == 0) ? g_q : (blockIdx.z == 1) ? g_k : g_v;
    } else {
        A   = g_o;
        Bm  = W0;
        Out = Cout;
    }

    // Loader mapping.
    const int arow = tid >> 1;           // 0..127
    const int akk  = (tid & 1) * 4;      // 0 or 4
    const int brow = tid >> 5;           // 0..7
    const int bcol = (tid & 31) * 4;     // 0..124

    const float* Aptr = A + (m0 + arow) * LDA + akk;
    const float* Bptr = Bm + brow * LDA + n0 + bcol;

    // Initial global fetch (k0 = 0)
    float4 a0 = *(const float4*)(Aptr);
    float4 a1 = *(const float4*)(Aptr + 8);
    float4 b0 = *(const float4*)(Bptr);
    float4 b1 = *(const float4*)(Bptr + 8 * LDA);

    // Stage into buffer 0
    As[0][akk + 0][arow] = a0.x;
    As[0][akk + 1][arow] = a0.y;
    As[0][akk + 2][arow] = a0.z;
    As[0][akk + 3][arow] = a0.w;
    As[0][akk + 8][arow] = a1.x;
    As[0][akk + 9][arow] = a1.y;
    As[0][akk + 10][arow] = a1.z;
    As[0][akk + 11][arow] = a1.w;
    *(float4*)&Bs[0][brow][bcol]     = b0;
    *(float4*)&Bs[0][brow + 8][bcol] = b1;
    __syncthreads();

    float acc[8][8];
#pragma unroll
    for (int i = 0; i < 8; i++)
#pragma unroll
        for (int j = 0; j < 8; j++) acc[i][j] = 0.0f;

    int buf = 0;
    for (int k0 = 16;; k0 += 16) {
        const bool more = (k0 < LDA);
        if (more) {                      // prefetch next tile into registers
            a0 = *(const float4*)(Aptr + k0);
            a1 = *(const float4*)(Aptr + k0 + 8);
            b0 = *(const float4*)(Bptr + k0 * LDA);
            b1 = *(const float4*)(Bptr + (k0 + 8) * LDA);
        }

#pragma unroll
        for (int kk = 0; kk < 16; kk++) {
            float a[8], b[8];
            *(float4*)&a[0] = *(const float4*)&As[buf][kk][ty * 8];
            *(float4*)&a[4] = *(const float4*)&As[buf][kk][ty * 8 + 4];
            *(float4*)&b[0] = *(const float4*)&Bs[buf][kk][tx * 4];
            *(float4*)&b[4] = *(const float4*)&Bs[buf][kk][64 + tx * 4];
#pragma unroll
            for (int i = 0; i < 8; i++)
#pragma unroll
                for (int j = 0; j < 8; j++)
                    acc[i][j] = fmaf(a[i], b[j], acc[i][j]);
        }

        if (!more) break;

        buf ^= 1;                        // stage prefetched tile into other buffer
        As[buf][akk + 0][arow] = a0.x;
        As[buf][akk + 1][arow] = a0.y;
        As[buf][akk + 2][arow] = a0.z;
        As[buf][akk + 3][arow] = a0.w;
        As[buf][akk + 8][arow] = a1.x;
        As[buf][akk + 9][arow] = a1.y;
        As[buf][akk + 10][arow] = a1.z;
        As[buf][akk + 11][arow] = a1.w;
        *(float4*)&Bs[buf][brow][bcol]     = b0;
        *(float4*)&Bs[buf][brow + 8][bcol] = b1;
        __syncthreads();
    }

    // Epilogue: two 4-wide column chunks per row (cols tx*4 and 64+tx*4).
#pragma unroll
    for (int i = 0; i < 8; i++) {
        const int row = m0 + ty * 8 + i;
        float4 lo = make_float4(acc[i][0], acc[i][1], acc[i][2], acc[i][3]);
        float4 hi = make_float4(acc[i][4], acc[i][5], acc[i][6], acc[i][7]);
        if (MODE == 0) {
            const int b = row >> 11;
            const int t = row & (Tdim - 1);
            const int n_lo = n0 + tx * 4;        // 4-wide chunk never crosses a head
            const int n_hi = n_lo + 64;
            float* dst_lo = Out + (((b * Hn + (n_lo >> 6)) * Tdim + t) << 6) + (n_lo & 63);
            float* dst_hi = Out + (((b * Hn + (n_hi >> 6)) * Tdim + t) << 6) + (n_hi & 63);
            *(float4*)dst_lo = lo;
            *(float4*)dst_hi = hi;
        } else {
            float* dst = Out + row * ND + n0 + tx * 4;
            *(float4*)dst        = lo;
            *(float4*)(dst + 64) = hi;
        }
    }
}

// ---------------------------------------------------------------------------
// Flash attention, fp32, causal, scale = +sqrt(dk) = 8 (faithful to source).
// One block = 128 query rows of one (b,h); one thread owns one query row.
// K/V tiles (64x64) in shared; per-row score vector spilled to padded shared.
//
// R9: flattened 1-D grid with HEAVIEST-FIRST block ordering. Work per block
// is proportional to its causal tile count (xblk+1); launching large-xblk
// blocks first makes greedy block scheduling approximate LPT and removes the
// ~40% end-of-kernel tail where a 16-tile block started in the last wave.
// Per-block arithmetic is bit-identical to the previous (passing) version.
// ---------------------------------------------------------------------------
__global__ void __launch_bounds__(128) attn_kernel()
{
    extern __shared__ float sm[];
    float* Ks = sm;                    // BC*DKn
    float* Vs = sm + BC * DKn;         // BC*DKn
    float* Ss = sm + 2 * BC * DKn;     // BR*(BC+1), pad avoids bank conflicts

    // Heaviest-first remap: bids 0..31 -> xblk=15 (16 tiles), next 32 -> 14, ...
    const int bid  = blockIdx.x;
    const int xblk = (NXBLK - 1) - (bid >> 5);   // 15 down to 0
    const int bh   = bid & (NBH - 1);            // 0..31

    const int i0  = xblk * BR;
    const int tid = threadIdx.x;
    const int i   = i0 + tid;          // this thread's query row

    const float4* qrow = (const float4*)(g_q + (bh * Tdim + i) * DKn);
    float4 q4[16];
#pragma unroll
    for (int dd = 0; dd < 16; dd++) q4[dd] = qrow[dd];

    float4 o4[16];
#pragma unroll
    for (int dd = 0; dd < 16; dd++) o4[dd] = make_float4(0.f, 0.f, 0.f, 0.f);
    float m = -1e30f, l = 0.f;

    const int ntiles = (i0 + BR) / BC;
    const float4* kg0 = (const float4*)(g_k + bh * Tdim * DKn);
    const float4* vg0 = (const float4*)(g_v + bh * Tdim * DKn);
    float* srow = Ss + tid * (BC + 1);

    for (int tile = 0; tile < ntiles; tile++) {
        const int j0 = tile * BC;
        const float4* kg = kg0 + j0 * (DKn / 4);
        const float4* vg = vg0 + j0 * (DKn / 4);
#pragma unroll
        for (int r = 0; r < 8; r++) {           // 1024 float4 each, coalesced
            ((float4*)Ks)[tid + r * 128] = kg[tid + r * 128];
            ((float4*)Vs)[tid + r * 128] = vg[tid + r * 128];
        }
        __syncthreads();

        const int jlim = i - j0;                // valid keys: j <= jlim
        float tmax = -1e30f;
#pragma unroll 2
        for (int j = 0; j < BC; j++) {
            const float4* kr = (const float4*)(Ks + j * DKn);  // warp-broadcast reads
            float4 s4 = make_float4(0.f, 0.f, 0.f, 0.f);
#pragma unroll
            for (int dd = 0; dd < 16; dd++) {
                float4 kv = kr[dd];
                s4.x = fmaf(q4[dd].x, kv.x, s4.x);
                s4.y = fmaf(q4[dd].y, kv.y, s4.y);
                s4.z = fmaf(q4[dd].z, kv.z, s4.z);
                s4.w = fmaf(q4[dd].w, kv.w, s4.w);
            }
            float s = ((s4.x + s4.y) + (s4.z + s4.w)) * 8.0f;   // x sqrt(dk)
            if (j > jlim) s = -1e30f;                           // causal mask
            srow[j] = s;
            tmax = fmaxf(tmax, s);
        }

        const float mnew  = fmaxf(m, tmax);
        const float alpha = __expf(m - mnew);   // 0 on first live tile, 1 if max unchanged
#pragma unroll
        for (int dd = 0; dd < 16; dd++) {
            o4[dd].x *= alpha; o4[dd].y *= alpha;
            o4[dd].z *= alpha; o4[dd].w *= alpha;
        }
        float lsum = 0.f;
#pragma unroll 2
        for (int j = 0; j < BC; j++) {
            const float p = __expf(srow[j] - mnew);             // masked -> 0
            lsum += p;
            const float4* vr = (const float4*)(Vs + j * DKn);   // warp-broadcast reads
#pragma unroll
            for (int dd = 0; dd < 16; dd++) {
                float4 vv = vr[dd];
                o4[dd].x = fmaf(p, vv.x, o4[dd].x);
                o4[dd].y = fmaf(p, vv.y, o4[dd].y);
                o4[dd].z = fmaf(p, vv.z, o4[dd].z);
                o4[dd].w = fmaf(p, vv.w, o4[dd].w);
            }
        }
        l = l * alpha + lsum;
        m = mnew;
        __syncthreads();
    }

    const float inv = 1.0f / l;
    const int b = bh >> 4;
    const int h = bh & 15;
    float4* dst = (float4*)(g_o + (b * Tdim + i) * ND + h * DKn);
#pragma unroll
    for (int dd = 0; dd < 16; dd++) {
        float4 v = o4[dd];
        dst[dd] = make_float4(v.x * inv, v.y * inv, v.z * inv, v.w * inv);
    }
}

// ---------------------------------------------------------------------------
extern "C" void kernel_launch(void* const* d_in, const int* in_sizes, int n_in,
                              void* d_out, int out_size)
{
    const float* x  = (const float*)d_in[0];
    const float* Wq = (const float*)d_in[1];
    const float* Wk = (const float*)d_in[2];
    const float* Wv = (const float*)d_in[3];
    const float* Wo = (const float*)d_in[4];
    float* out = (float*)d_out;

    // Idempotent, host-side, deterministic: needed for 66 KB dynamic smem.
    cudaFuncSetAttribute(attn_kernel, cudaFuncAttributeMaxDynamicSharedMemorySize,
                         SMEM_ATTN);

    // Q/K/V projections: one GEMM grid, z selects weight matrix & destination.
    gemm_kernel<0><<<dim3(ND / 128, BT / 128, 3), 256>>>(x, Wq, Wk, Wv, nullptr);

    // Causal attention, flattened grid, heaviest blocks launched first.
    attn_kernel<<<NXBLK * NBH, 128, SMEM_ATTN>>>();

    // Output projection: g_o [BT x ND] @ linear_m1 [ND x OUT].
    gemm_kernel<1><<<dim3(ND / 128, BT / 128, 1), 256>>>(nullptr, Wo, nullptr, nullptr, out);
}

// round 13
// speedup vs baseline: 1.4068x; 1.1499x over previous
#include <cuda_runtime.h>

// Problem dims
#define Bn   2
#define Tdim 2048
#define Cdim 1024
#define Hn   16
#define DKn  64
#define ND   1024   // H*DK == OUT
#define BT   4096   // Bn*Tdim
#define LDA  1024   // both GEMM A matrices and B matrices have 1024 stride

// Attention tiling
#define BR 128
#define BC 64
#define NXBLK (Tdim / BR)                                // 16 row-blocks per (b,h)
#define NBH   (Bn * Hn)                                  // 32

// Attention smem layout (floats)
#define OFF_QT 0                      // Qt[64][132]  (Q transposed, padded)
#define OFF_KT 8448                   // Kt[64][68]   (K transposed, padded)
#define OFF_VS 12800                  // Vs[64][68]   (V row-major, padded)
#define OFF_SS 17152                  // Ss[128][68]  (S, then P in-place)
#define OFF_AB 25856                  // alpha[128]
#define OFF_LB 25984                  // linv[128]
#define ATTN_SMEM_FLOATS 26112
#define SMEM_ATTN (ATTN_SMEM_FLOATS * 4)   // 104448 bytes -> 2 CTAs/SM

// A-tile padded stride for SGEMM: 132 floats (16B-aligned rows, conflict-free)
#define ASTR 132

// Scratch (device globals: allocation-free per harness rules)
__device__ float g_q[Bn * Hn * Tdim * DKn];
__device__ float g_k[Bn * Hn * Tdim * DKn];
__device__ float g_v[Bn * Hn * Tdim * DKn];
__device__ float g_o[Bn * Tdim * ND];

// ---------------------------------------------------------------------------
// 128x128x16 register-tiled SGEMM, 256 threads, 8x8 microtile,
// double-buffered shared memory, ONE __syncthreads per k-iteration.
// (unchanged from the passing R9 kernel)
// ---------------------------------------------------------------------------
template <int MODE>
__global__ void __launch_bounds__(256, 2) gemm_kernel(const float* __restrict__ Ain,
                                                      const float* __restrict__ W0,
                                                      const float* __restrict__ W1,
                                                      const float* __restrict__ W2,
                                                      float* __restrict__ Cout)
{
    __shared__ float As[2][16][ASTR];
    __shared__ float Bs[2][16][128];

    const int tid = threadIdx.x;
    const int tx  = tid & 15;
    const int ty  = tid >> 4;
    const int m0  = blockIdx.y * 128;
    const int n0  = blockIdx.x * 128;

    const float* A;
    const float* Bm;
    float* Out;
    if (MODE == 0) {
        A   = Ain;
        Bm  = (blockIdx.z == 0) ? W0 : (blockIdx.z == 1) ? W1 : W2;
        Out = (blockIdx.z == 0) ? g_q : (blockIdx.z == 1) ? g_k : g_v;
    } else {
        A   = g_o;
        Bm  = W0;
        Out = Cout;
    }

    const int arow = tid >> 1;
    const int akk  = (tid & 1) * 4;
    const int brow = tid >> 5;
    const int bcol = (tid & 31) * 4;

    const float* Aptr = A + (m0 + arow) * LDA + akk;
    const float* Bptr = Bm + brow * LDA + n0 + bcol;

    float4 a0 = *(const float4*)(Aptr);
    float4 a1 = *(const float4*)(Aptr + 8);
    float4 b0 = *(const float4*)(Bptr);
    float4 b1 = *(const float4*)(Bptr + 8 * LDA);

    As[0][akk + 0][arow] = a0.x;
    As[0][akk + 1][arow] = a0.y;
    As[0][akk + 2][arow] = a0.z;
    As[0][akk + 3][arow] = a0.w;
    As[0][akk + 8][arow] = a1.x;
    As[0][akk + 9][arow] = a1.y;
    As[0][akk + 10][arow] = a1.z;
    As[0][akk + 11][arow] = a1.w;
    *(float4*)&Bs[0][brow][bcol]     = b0;
    *(float4*)&Bs[0][brow + 8][bcol] = b1;
    __syncthreads();

    float acc[8][8];
#pragma unroll
    for (int i = 0; i < 8; i++)
#pragma unroll
        for (int j = 0; j < 8; j++) acc[i][j] = 0.0f;

    int buf = 0;
    for (int k0 = 16;; k0 += 16) {
        const bool more = (k0 < LDA);
        if (more) {
            a0 = *(const float4*)(Aptr + k0);
            a1 = *(const float4*)(Aptr + k0 + 8);
            b0 = *(const float4*)(Bptr + k0 * LDA);
            b1 = *(const float4*)(Bptr + (k0 + 8) * LDA);
        }

#pragma unroll
        for (int kk = 0; kk < 16; kk++) {
            float a[8], b[8];
            *(float4*)&a[0] = *(const float4*)&As[buf][kk][ty * 8];
            *(float4*)&a[4] = *(const float4*)&As[buf][kk][ty * 8 + 4];
            *(float4*)&b[0] = *(const float4*)&Bs[buf][kk][tx * 4];
            *(float4*)&b[4] = *(const float4*)&Bs[buf][kk][64 + tx * 4];
#pragma unroll
            for (int i = 0; i < 8; i++)
#pragma unroll
                for (int j = 0; j < 8; j++)
                    acc[i][j] = fmaf(a[i], b[j], acc[i][j]);
        }

        if (!more) break;

        buf ^= 1;
        As[buf][akk + 0][arow] = a0.x;
        As[buf][akk + 1][arow] = a0.y;
        As[buf][akk + 2][arow] = a0.z;
        As[buf][akk + 3][arow] = a0.w;
        As[buf][akk + 8][arow] = a1.x;
        As[buf][akk + 9][arow] = a1.y;
        As[buf][akk + 10][arow] = a1.z;
        As[buf][akk + 11][arow] = a1.w;
        *(float4*)&Bs[buf][brow][bcol]     = b0;
        *(float4*)&Bs[buf][brow + 8][bcol] = b1;
        __syncthreads();
    }

#pragma unroll
    for (int i = 0; i < 8; i++) {
        const int row = m0 + ty * 8 + i;
        float4 lo = make_float4(acc[i][0], acc[i][1], acc[i][2], acc[i][3]);
        float4 hi = make_float4(acc[i][4], acc[i][5], acc[i][6], acc[i][7]);
        if (MODE == 0) {
            const int b = row >> 11;
            const int t = row & (Tdim - 1);
            const int n_lo = n0 + tx * 4;
            const int n_hi = n_lo + 64;
            float* dst_lo = Out + (((b * Hn + (n_lo >> 6)) * Tdim + t) << 6) + (n_lo & 63);
            float* dst_hi = Out + (((b * Hn + (n_hi >> 6)) * Tdim + t) << 6) + (n_hi & 63);
            *(float4*)dst_lo = lo;
            *(float4*)dst_hi = hi;
        } else {
            float* dst = Out + row * ND + n0 + tx * 4;
            *(float4*)dst        = lo;
            *(float4*)(dst + 64) = hi;
        }
    }
}

// ---------------------------------------------------------------------------
// Flash attention v2: both S = Q*K^T and O += P*V as register-tiled mini-GEMMs
// (microtile 8 rows x 4 cols per thread, 256 threads), softmax row-wise by
// thread pairs with in-place exp over the S buffer. Causal, scale = +8.
// Heaviest-first LPT block order retained.
// ---------------------------------------------------------------------------
__global__ void __launch_bounds__(256) attn_kernel()
{
    extern __shared__ float sm[];
    float* Qt = sm + OFF_QT;     // [64][132]  Qt[d][row]
    float* Kt = sm + OFF_KT;     // [64][68]   Kt[d][j]
    float* Vs = sm + OFF_VS;     // [64][68]   Vs[j][d]
    float* Ss = sm + OFF_SS;     // [128][68]  S[row][j], exp'd in place
    float* Ab = sm + OFF_AB;     // alpha[128]
    float* Lb = sm + OFF_LB;     // linv[128]

    // LPT remap: heaviest (xblk=15) blocks first.
    const int bid  = blockIdx.x;
    const int xblk = (NXBLK - 1) - (bid >> 5);
    const int bh   = bid & (NBH - 1);
    const int i0   = xblk * BR;

    const int tid = threadIdx.x;
    const int tx  = tid & 15;          // col group (4 cols)
    const int ty  = tid >> 4;          // row group (8 rows)

    // ---- Load Q block transposed into Qt (STS conflict-free mapping) ----
    const float* qg = g_q + (bh * Tdim + i0) * DKn;
#pragma unroll
    for (int t = 0; t < 8; t++) {
        const int idx = tid + t * 256;         // 0..2047
        const int row = idx & 127;
        const int d4  = idx >> 7;              // 0..15
        float4 v = *(const float4*)(qg + row * DKn + d4 * 4);
        Qt[(d4 * 4 + 0) * 132 + row] = v.x;
        Qt[(d4 * 4 + 1) * 132 + row] = v.y;
        Qt[(d4 * 4 + 2) * 132 + row] = v.z;
        Qt[(d4 * 4 + 3) * 132 + row] = v.w;
    }

    float o_acc[8][4];
#pragma unroll
    for (int i = 0; i < 8; i++)
#pragma unroll
        for (int j = 0; j < 4; j++) o_acc[i][j] = 0.0f;

    float m_st = -1e30f, l_st = 0.0f;  // per-pair row state (duplicated in pair)
    const int r_sm = tid >> 1;         // softmax row owned by this thread pair
    const int jh   = (tid & 1) * 8;    // float4-chunk half: 0..7 or 8..15

    const int ntiles = 2 * (xblk + 1);
    const float* kgb = g_k + bh * Tdim * DKn;
    const float* vgb = g_v + bh * Tdim * DKn;

    for (int tile = 0; tile < ntiles; tile++) {
        const int j0 = tile * BC;
        __syncthreads();   // prev tile's PV done: safe to overwrite Kt/Vs/Ss

        // ---- stage K transposed ----
#pragma unroll
        for (int t = 0; t < 4; t++) {
            const int idx = tid + t * 256;     // 0..1023
            const int j  = idx & 63;
            const int d4 = idx >> 6;           // 0..15
            float4 v = *(const float4*)(kgb + (j0 + j) * DKn + d4 * 4);
            Kt[(d4 * 4 + 0) * 68 + j] = v.x;
            Kt[(d4 * 4 + 1) * 68 + j] = v.y;
            Kt[(d4 * 4 + 2) * 68 + j] = v.z;
            Kt[(d4 * 4 + 3) * 68 + j] = v.w;
        }
        // ---- stage V row-major ----
#pragma unroll
        for (int t = 0; t < 4; t++) {
            const int idx = tid + t * 256;
            const int j  = idx >> 4;           // 0..63
            const int d4 = idx & 15;
            *(float4*)(Vs + j * 68 + d4 * 4) =
                *(const float4*)(vgb + (j0 + j) * DKn + d4 * 4);
        }
        __syncthreads();

        // ---- S-GEMM: S[128x64] = Q[128x64] * K^T ----
        float acc[8][4];
#pragma unroll
        for (int i = 0; i < 8; i++)
#pragma unroll
            for (int j = 0; j < 4; j++) acc[i][j] = 0.0f;

#pragma unroll 4
        for (int kk = 0; kk < 64; kk++) {
            float a[8];
            *(float4*)&a[0] = *(const float4*)(Qt + kk * 132 + ty * 8);
            *(float4*)&a[4] = *(const float4*)(Qt + kk * 132 + ty * 8 + 4);
            const float4 b4 = *(const float4*)(Kt + kk * 68 + tx * 4);
#pragma unroll
            for (int i = 0; i < 8; i++) {
                acc[i][0] = fmaf(a[i], b4.x, acc[i][0]);
                acc[i][1] = fmaf(a[i], b4.y, acc[i][1]);
                acc[i][2] = fmaf(a[i], b4.z, acc[i][2]);
                acc[i][3] = fmaf(a[i], b4.w, acc[i][3]);
            }
        }

        // store S scaled (+sqrt(dk) = *8) with causal mask
        const int gj = j0 + tx * 4;
#pragma unroll
        for (int i = 0; i < 8; i++) {
            const int gi = i0 + ty * 8 + i;
            float4 s;
            s.x = (gj + 0 <= gi) ? acc[i][0] * 8.0f : -1e30f;
            s.y = (gj + 1 <= gi) ? acc[i][1] * 8.0f : -1e30f;
            s.z = (gj + 2 <= gi) ? acc[i][2] * 8.0f : -1e30f;
            s.w = (gj + 3 <= gi) ? acc[i][3] * 8.0f : -1e30f;
            *(float4*)(Ss + (ty * 8 + i) * 68 + tx * 4) = s;
        }
        __syncthreads();

        // ---- softmax: pair (tid, tid^1) handles row r_sm, half jh each ----
        {
            float4* Srow = (float4*)(Ss + r_sm * 68);
            float mx = -1e30f;
#pragma unroll
            for (int t = 0; t < 8; t++) {
                float4 s = Srow[jh + t];
                mx = fmaxf(mx, fmaxf(fmaxf(s.x, s.y), fmaxf(s.z, s.w)));
            }
            mx = fmaxf(mx, __shfl_xor_sync(0xffffffffu, mx, 1));
            const float mnew  = fmaxf(m_st, mx);
            const float alpha = __expf(m_st - mnew);
            Ab[r_sm] = alpha;                       // both pair threads: same value
            float ls = 0.0f;
#pragma unroll
            for (int t = 0; t < 8; t++) {
                float4 s = Srow[jh + t];
                s.x = __expf(s.x - mnew);
                s.y = __expf(s.y - mnew);
                s.z = __expf(s.z - mnew);
                s.w = __expf(s.w - mnew);
                ls += (s.x + s.y) + (s.z + s.w);
                Srow[jh + t] = s;                   // in-place P
            }
            ls += __shfl_xor_sync(0xffffffffu, ls, 1);
            l_st = l_st * alpha + ls;
            m_st = mnew;
        }
        __syncthreads();

        // ---- rescale O by alpha(row) ----
        {
            float ar[8];
#pragma unroll
            for (int i = 0; i < 8; i++) ar[i] = Ab[ty * 8 + i];
#pragma unroll
            for (int i = 0; i < 8; i++)
#pragma unroll
                for (int j = 0; j < 4; j++) o_acc[i][j] *= ar[i];
        }

        // ---- PV-GEMM: O[128x64] += P[128x64] * V[64x64], kk vectorized x4 ----
#pragma unroll 2
        for (int k4 = 0; k4 < 16; k4++) {
            float4 av[8];
#pragma unroll
            for (int i = 0; i < 8; i++)
                av[i] = *(const float4*)(Ss + (ty * 8 + i) * 68 + k4 * 4);
            float4 bv0 = *(const float4*)(Vs + (k4 * 4 + 0) * 68 + tx * 4);
            float4 bv1 = *(const float4*)(Vs + (k4 * 4 + 1) * 68 + tx * 4);
            float4 bv2 = *(const float4*)(Vs + (k4 * 4 + 2) * 68 + tx * 4);
            float4 bv3 = *(const float4*)(Vs + (k4 * 4 + 3) * 68 + tx * 4);
#pragma unroll
            for (int i = 0; i < 8; i++) {
                o_acc[i][0] = fmaf(av[i].x, bv0.x, o_acc[i][0]);
                o_acc[i][1] = fmaf(av[i].x, bv0.y, o_acc[i][1]);
                o_acc[i][2] = fmaf(av[i].x, bv0.z, o_acc[i][2]);
                o_acc[i][3] = fmaf(av[i].x, bv0.w, o_acc[i][3]);
                o_acc[i][0] = fmaf(av[i].y, bv1.x, o_acc[i][0]);
                o_acc[i][1] = fmaf(av[i].y, bv1.y, o_acc[i][1]);
                o_acc[i][2] = fmaf(av[i].y, bv1.z, o_acc[i][2]);
                o_acc[i][3] = fmaf(av[i].y, bv1.w, o_acc[i][3]);
                o_acc[i][0] = fmaf(av[i].z, bv2.x, o_acc[i][0]);
                o_acc[i][1] = fmaf(av[i].z, bv2.y, o_acc[i][1]);
                o_acc[i][2] = fmaf(av[i].z, bv2.z, o_acc[i][2]);
                o_acc[i][3] = fmaf(av[i].z, bv2.w, o_acc[i][3]);
                o_acc[i][0] = fmaf(av[i].w, bv3.x, o_acc[i][0]);
                o_acc[i][1] = fmaf(av[i].w, bv3.y, o_acc[i][1]);
                o_acc[i][2] = fmaf(av[i].w, bv3.z, o_acc[i][2]);
                o_acc[i][3] = fmaf(av[i].w, bv3.w, o_acc[i][3]);
            }
        }
    }

    // ---- epilogue: divide by l, write to g_o in [B,T,H*DK] layout ----
    Lb[r_sm] = 1.0f / l_st;            // pair-duplicated identical write
    __syncthreads();
    float li[8];
#pragma unroll
    for (int i = 0; i < 8; i++) li[i] = Lb[ty * 8 + i];

    const int b = bh >> 4;
    const int h = bh & 15;
    float* og = g_o + (b * Tdim + i0 + ty * 8) * ND + h * DKn + tx * 4;
#pragma unroll
    for (int i = 0; i < 8; i++) {
        float4 o;
        o.x = o_acc[i][0] * li[i];
        o.y = o_acc[i][1] * li[i];
        o.z = o_acc[i][2] * li[i];
        o.w = o_acc[i][3] * li[i];
        *(float4*)(og + i * ND) = o;
    }
}

// ---------------------------------------------------------------------------
extern "C" void kernel_launch(void* const* d_in, const int* in_sizes, int n_in,
                              void* d_out, int out_size)
{
    const float* x  = (const float*)d_in[0];
    const float* Wq = (const float*)d_in[1];
    const float* Wk = (const float*)d_in[2];
    const float* Wv = (const float*)d_in[3];
    const float* Wo = (const float*)d_in[4];
    float* out = (float*)d_out;

    // Idempotent, host-side, deterministic: needed for 102 KB dynamic smem.
    cudaFuncSetAttribute(attn_kernel, cudaFuncAttributeMaxDynamicSharedMemorySize,
                         SMEM_ATTN);

    // Q/K/V projections: one GEMM grid, z selects weight matrix & destination.
    gemm_kernel<0><<<dim3(ND / 128, BT / 128, 3), 256>>>(x, Wq, Wk, Wv, nullptr);

    // Causal attention, flattened grid, heaviest blocks launched first.
    attn_kernel<<<NXBLK * NBH, 256, SMEM_ATTN>>>();

    // Output projection: g_o [BT x ND] @ linear_m1 [ND x OUT].
    gemm_kernel<1><<<dim3(ND / 128, BT / 128, 1), 256>>>(nullptr, Wo, nullptr, nullptr, out);
}